// round 12
// baseline (speedup 1.0000x reference)
#include <cuda_runtime.h>
#include <cooperative_groups.h>
namespace cg = cooperative_groups;

#define BB 8
#define HH 256
#define WW 256
#define NPIX (BB*HH*WW)
#define N_ITERS 200
#define TT 4                 // halo width / sub-iterations per exchange
#define NB (N_ITERS/TT)      // 50 exchange rounds
#define NCTAS 256            // 8 images * (4x8) 32x64 tiles, 2 CTAs/SM
#define NTHREADS 288         // 9 warps; warp = 8 cols x 40 rows slab
#define RPT 10               // rows per thread (1 col)
#define EXT_H 40
#define EXT_W 72

// Double-buffered full-state exchange arrays (alloc-free scratch)
__device__ float gU [2][NPIX];
__device__ float gUB[2][NPIX];
__device__ float gP [2][NPIX];
__device__ float gQ [2][NPIX];

__device__ __forceinline__ float clipf(float v, float b) {
    return fminf(fmaxf(v, -b), b);
}
__device__ __forceinline__ float ldcg(const float* p) {
    float v;
    asm volatile("ld.global.cg.f32 %0, [%1];" : "=f"(v) : "l"(p) : "memory");
    return v;
}

__global__ __launch_bounds__(NTHREADS, 2)
void tv_block(const float* __restrict__ f,
              const float* __restrict__ lam,
              float* __restrict__ out)
{
    cg::grid_group grid = cg::this_grid();
    const unsigned FULL = 0xffffffffu;

    const float SIG  = 0.35355339f;
    const float TAUc = 0.35355339f;
    const float INV  = 1.0f / (1.0f + TAUc);

    // Cross-warp edge arrays, indexed by [warp][ext row] (R11 bug: was [warp][k],
    // which made the 4 row-groups of a warp collide). Single-buffered; the two
    // per-sub-iter __syncthreads separate every rewrite from the preceding read.
    __shared__ float ubEdge[10][EXT_H];  // [w][r]: ub of col 8w (lane c8=0); w=9 pad = 0
    __shared__ float qEdge [10][EXT_H];  // [w+1][r]: q of col 8w+7 (c8=7); w=0 pad = 0

    const int cta = blockIdx.x;
    const int img = cta >> 5;
    const int t   = cta & 31;
    const int i0  = (t >> 2) * 32;
    const int j0  = (t & 3) * 64;
    const int tid  = threadIdx.x;
    const int w    = tid >> 5;         // warp 0..8
    const int lane = tid & 31;
    const int c8   = lane & 7;         // col within slab
    const int rgl  = lane >> 3;        // row group 0..3
    const int col  = 8 * w + c8;       // ext col 0..71
    const int rb   = RPT * rgl;        // first ext row of my strip

    const int gi_top = i0 - TT + rb;
    const int gj     = j0 - TT + col;
    const int base   = (img * HH + gi_top) * WW + gj;   // cell k at base + k*WW

    for (int x = tid; x < 10 * EXT_H; x += NTHREADS) {
        ((float*)ubEdge)[x] = 0.f;
        ((float*)qEdge )[x] = 0.f;
    }

    // ---- per-cell state in registers ----
    float u[RPT], ub[RPT], p[RPT], q[RPT], fv[RPT], lx[RPT], ly[RPT];
#pragma unroll
    for (int k = 0; k < RPT; k++) {
        const int gi  = gi_top + k;
        const bool ii = (gi >= 0 && gi < HH && gj >= 0 && gj < WW);
        const int idx = base + k * WW;
        const float fk = ii ? f[idx] : 0.f;
        fv[k] = fk; u[k] = fk; ub[k] = fk; p[k] = 0.f; q[k] = 0.f;
        lx[k] = (ii && gi < HH - 1) ? lam[idx + WW] : 0.f;  // bound for p(r,c)
        ly[k] = (ii && gj < WW - 1) ? lam[idx + 1]  : 0.f;  // bound for q(r,c)
    }
    __syncthreads();   // smem zeros visible

#pragma unroll 1
    for (int blk = 0; blk < NB; blk++) {
        if (blk) {
            const int sb = blk & 1;
            // ---- publish interior frame (width-TT border of true tile) ----
#pragma unroll
            for (int k = 0; k < RPT; k++) {
                const int r = rb + k;
                const bool interior = (r >= TT && r < EXT_H - TT &&
                                       col >= TT && col < EXT_W - TT);
                if (interior && (r < 2*TT || r >= EXT_H - 2*TT ||
                                 col < 2*TT || col >= EXT_W - 2*TT)) {
                    const int idx = base + k * WW;
                    gU [sb][idx] = u[k];  gUB[sb][idx] = ub[k];
                    gP [sb][idx] = p[k];  gQ [sb][idx] = q[k];
                }
            }
            grid.sync();
            // ---- refresh ring (full state) — registers only ----
#pragma unroll
            for (int k = 0; k < RPT; k++) {
                const int r  = rb + k;
                const int gi = gi_top + k;
                const bool ring = (r < TT || r >= EXT_H - TT ||
                                   col < TT || col >= EXT_W - TT);
                if (ring && gi >= 0 && gi < HH && gj >= 0 && gj < WW) {
                    const int idx = base + k * WW;
                    u[k]  = ldcg(&gU [sb][idx]);
                    ub[k] = ldcg(&gUB[sb][idx]);
                    p[k]  = ldcg(&gP [sb][idx]);
                    q[k]  = ldcg(&gQ [sb][idx]);
                }
            }
        }

#pragma unroll 1
        for (int s = 0; s < TT; s++) {
            // ---- (a) publish left-edge ub for left warp's c8=7 lanes ----
            if (c8 == 0) {
#pragma unroll
                for (int k = 0; k < RPT; k++) ubEdge[w][rb + k] = ub[k];
            }
            __syncthreads();

            // ---- (b) dual update (p, q): neighbors via shfl ----
            const float ub_below = __shfl_down_sync(FULL, ub[0], 8); // row rb+10
#pragma unroll
            for (int k = 0; k < RPT; k++) {
                float ub_r = __shfl_down_sync(FULL, ub[k], 1);
                if (c8 == 7) ub_r = ubEdge[w + 1][rb + k];  // w=8 pad = 0
                const float ub_b = (k < RPT - 1) ? ub[k + 1] : ub_below;
                p[k] = clipf(p[k] + SIG * (ub_b - ub[k]), lx[k]);
                q[k] = clipf(q[k] + SIG * (ub_r - ub[k]), ly[k]);
            }
            if (c8 == 7) {
#pragma unroll
                for (int k = 0; k < RPT; k++) qEdge[w + 1][rb + k] = q[k];
            }
            __syncthreads();

            // ---- (c) primal update (u, ubar) ----
            float pu = __shfl_up_sync(FULL, p[RPT - 1], 8);  // p(rb-1)
            if (rgl == 0) pu = 0.f;                          // ext-outside garbage row
#pragma unroll
            for (int k = 0; k < RPT; k++) {
                float q_l = __shfl_up_sync(FULL, q[k], 1);
                if (c8 == 0) q_l = qEdge[w][rb + k];         // w=0 pad = 0
                const float div = (pu - p[k]) + (q_l - q[k]);
                const float un  = (u[k] + TAUc * (fv[k] - div)) * INV;
                ub[k] = 2.f * un - u[k];
                u[k]  = un;
                pu    = p[k];
            }
        }
    }

    // ---- write interior result ----
#pragma unroll
    for (int k = 0; k < RPT; k++) {
        const int r = rb + k;
        if (r >= TT && r < EXT_H - TT && col >= TT && col < EXT_W - TT)
            out[base + k * WW] = u[k];
    }
}

extern "C" void kernel_launch(void* const* d_in, const int* in_sizes, int n_in,
                              void* d_out, int out_size) {
    const float* f   = (const float*)d_in[0];
    const float* lam = (const float*)d_in[1];
    float* out = (float*)d_out;

    void* args[] = { (void*)&f, (void*)&lam, (void*)&out };
    cudaLaunchCooperativeKernel((void*)tv_block,
                                dim3(NCTAS), dim3(NTHREADS),
                                args, 0, 0);
}

// round 13
// speedup vs baseline: 1.1509x; 1.1509x over previous
#include <cuda_runtime.h>
#include <cooperative_groups.h>
#include <cstdint>

#define BB 8
#define HH 256
#define WW 256
#define NPIX (BB*HH*WW)
#define N_ITERS 200
#define TT 4                 // halo width / sub-iterations per exchange
#define NB (N_ITERS/TT)      // 50 exchange rounds (49 barriers)
#define NCTAS 256            // 8 images * (4x8) 32x64 tiles, 2 CTAs/SM
#define NTHREADS 288         // 36 column-pairs x 8 row groups
#define RPT 5                // rows per thread (x2 cols = 10 cells)
#define EXT_H 40
#define EXT_W 72

// Double-buffered full-state exchange arrays (alloc-free scratch)
__device__ float gU [2][NPIX];
__device__ float gUB[2][NPIX];
__device__ float gP [2][NPIX];
__device__ float gQ [2][NPIX];

// Per-image barrier counters, one 128B line each (zero-initialized).
struct __align__(128) ImgLine { unsigned long long v; unsigned long long pad[15]; };
__device__ ImgLine g_arr[BB];

__device__ __forceinline__ float clipf(float v, float b) {
    return fminf(fmaxf(v, -b), b);
}
__device__ __forceinline__ float ldcg(const float* p) {
    float v;
    asm volatile("ld.global.cg.f32 %0, [%1];" : "=f"(v) : "l"(p) : "memory");
    return v;
}
__device__ __forceinline__ unsigned long long ld_acq(const unsigned long long* p) {
    unsigned long long v;
    asm volatile("ld.acquire.gpu.global.u64 %0, [%1];" : "=l"(v) : "l"(p) : "memory");
    return v;
}
__device__ __forceinline__ void red_rel_add1(unsigned long long* p) {
    asm volatile("red.release.gpu.global.add.u64 [%0], %1;" :: "l"(p), "l"(1ULL) : "memory");
}

__global__ __launch_bounds__(NTHREADS, 2)
void tv_block(const float* __restrict__ f,
              const float* __restrict__ lam,
              float* __restrict__ out)
{
    const float SIG  = 0.35355339f;
    const float TAUc = 0.35355339f;
    const float INV  = 1.0f / (1.0f + TAUc);

    // Cross-thread arrays (only what neighbors actually read):
    __shared__ float ubE[EXT_H][37];   // ub of even ext col 2cp at [r][cp]; pad cp=36 (=0)
    __shared__ float qO [EXT_H][38];   // q of odd ext col 2cp+1 at [r][cp+1]; pad [r][0]
    __shared__ float ubB[9][EXT_W];    // first-row ub of each row group; pad rg=8
    __shared__ float pB [9][EXT_W];    // last-row p of each group at [rg+1][c]; pad [0]

    const int cta = blockIdx.x;
    const int img = cta >> 5;
    const int t   = cta & 31;
    const int i0  = (t >> 2) * 32;
    const int j0  = (t & 3) * 64;
    const int tid = threadIdx.x;
    const int cp  = tid % 36;          // column pair 0..35
    const int rg  = tid / 36;          // row group 0..7
    const int rb  = rg * RPT;          // first ext row of my strip
    const int c0  = 2 * cp;            // my even ext col

    const int gi_top = i0 - TT + rb;
    const int gj0    = j0 - TT + c0;
    const int base   = (img * HH + gi_top) * WW + gj0;  // cell (k,e) at base+k*WW+e

    // Barrier epoch (monotone counter; exact multiple at entry since each
    // launch fully drains before replay). Only tid 0 uses it.
    unsigned long long epoch = 0;
    if (tid == 0) epoch = *(volatile unsigned long long*)&g_arr[img].v;

    // Zero all SMEM (pads stay 0 = finite garbage for ring math)
    for (int x = tid; x < EXT_H * 37; x += NTHREADS) ((float*)ubE)[x] = 0.f;
    for (int x = tid; x < EXT_H * 38; x += NTHREADS) ((float*)qO )[x] = 0.f;
    for (int x = tid; x < 9 * EXT_W;  x += NTHREADS) ((float*)ubB)[x] = 0.f;
    for (int x = tid; x < 9 * EXT_W;  x += NTHREADS) ((float*)pB )[x] = 0.f;

    // ---- per-cell state in registers (n = 2k+e) ----
    float u[10], ub[10], p[10], q[10], fv[10], lx[10], ly[10];
#pragma unroll
    for (int k = 0; k < RPT; k++) {
#pragma unroll
        for (int e = 0; e < 2; e++) {
            const int n  = 2 * k + e;
            const int gi = gi_top + k, gj = gj0 + e;
            const bool ii = (gi >= 0 && gi < HH && gj >= 0 && gj < WW);
            const int idx = base + k * WW + e;
            const float fk = ii ? f[idx] : 0.f;
            fv[n] = fk; u[n] = fk; ub[n] = fk; p[n] = 0.f; q[n] = 0.f;
            lx[n] = (ii && gi < HH - 1) ? lam[idx + WW] : 0.f;  // bound for p(r,c)
            ly[n] = (ii && gj < WW - 1) ? lam[idx + 1]  : 0.f;  // bound for q(r,c)
        }
    }
    __syncthreads();   // zeros complete before targeted writes
#pragma unroll
    for (int k = 0; k < RPT; k++) ubE[rb + k][cp] = ub[2 * k];
    ubB[rg][c0] = ub[0]; ubB[rg][c0 + 1] = ub[1];
    __syncthreads();

#pragma unroll 1
    for (int blk = 0; blk < NB; blk++) {
        if (blk) {
            const int sb = blk & 1;
            // ---- publish interior frame (width-TT border of the true tile) ----
#pragma unroll
            for (int k = 0; k < RPT; k++) {
#pragma unroll
                for (int e = 0; e < 2; e++) {
                    const int n = 2 * k + e, r = rb + k, c = c0 + e;
                    const bool interior = (r >= TT && r < EXT_H - TT &&
                                           c >= TT && c < EXT_W - TT);
                    if (interior && (r < 2*TT || r >= EXT_H - 2*TT ||
                                     c < 2*TT || c >= EXT_W - 2*TT)) {
                        const int idx = base + k * WW + e;
                        gU [sb][idx] = u[n];  gUB[sb][idx] = ub[n];
                        gP [sb][idx] = p[n];  gQ [sb][idx] = q[n];
                    }
                }
            }
            __syncthreads();   // all publishes of this CTA complete

            // ---- per-image 32-CTA barrier (arrive + spin, monotone) ----
            if (tid == 0) {
                red_rel_add1(&g_arr[img].v);
                const unsigned long long tgt =
                    epoch + 32ULL * (unsigned long long)blk;
                while ((long long)(ld_acq(&g_arr[img].v) - tgt) < 0) { }
            }
            __syncthreads();   // release observed; ring reads ordered

            // ---- refresh ring (full state) from neighbors' publishes ----
#pragma unroll
            for (int k = 0; k < RPT; k++) {
#pragma unroll
                for (int e = 0; e < 2; e++) {
                    const int n = 2 * k + e, r = rb + k, c = c0 + e;
                    const int gi = gi_top + k, gj = gj0 + e;
                    const bool ring = (r < TT || r >= EXT_H - TT ||
                                       c < TT || c >= EXT_W - TT);
                    if (ring && gi >= 0 && gi < HH && gj >= 0 && gj < WW) {
                        const int idx = base + k * WW + e;
                        u[n]  = ldcg(&gU [sb][idx]);
                        ub[n] = ldcg(&gUB[sb][idx]);
                        p[n]  = ldcg(&gP [sb][idx]);
                        q[n]  = ldcg(&gQ [sb][idx]);
                        if (e == 0) ubE[r][cp] = ub[n];
                        if (k == 0) ubB[rg][c] = ub[n];
                    }
                }
            }
            __syncthreads();
        }

#pragma unroll 1
        for (int s = 0; s < TT; s++) {
            // ---- phase 1: dual update (p, q) ----
            const float ubb0 = ubB[rg + 1][c0];
            const float ubb1 = ubB[rg + 1][c0 + 1];
#pragma unroll
            for (int k = 0; k < RPT; k++) {
                const int r = rb + k;
                {   // even column: ub_right is own register ub[n+1]
                    const int n = 2 * k;
                    const float ub_b = (k < RPT - 1) ? ub[n + 2] : ubb0;
                    p[n] = clipf(p[n] + SIG * (ub_b     - ub[n]), lx[n]);
                    q[n] = clipf(q[n] + SIG * (ub[n + 1] - ub[n]), ly[n]);
                }
                {   // odd column: ub_right from right thread's even col
                    const int n = 2 * k + 1;
                    const float ub_b = (k < RPT - 1) ? ub[n + 2] : ubb1;
                    const float ub_r = ubE[r][cp + 1];
                    p[n] = clipf(p[n] + SIG * (ub_b - ub[n]), lx[n]);
                    q[n] = clipf(q[n] + SIG * (ub_r - ub[n]), ly[n]);
                    qO[r][cp + 1] = q[n];
                }
            }
            pB[rg + 1][c0]     = p[2 * (RPT - 1)];
            pB[rg + 1][c0 + 1] = p[2 * (RPT - 1) + 1];
            __syncthreads();

            // ---- phase 2: primal update (u, ubar) ----
            float pu0 = pB[rg][c0];
            float pu1 = pB[rg][c0 + 1];
#pragma unroll
            for (int k = 0; k < RPT; k++) {
                const int r = rb + k;
                const float qw = qO[r][cp];   // q(r, c0-1) from left thread
                {   // even column
                    const int n = 2 * k;
                    const float div = (pu0 - p[n]) + (qw - q[n]);
                    const float un  = (u[n] + TAUc * (fv[n] - div)) * INV;
                    ub[n] = 2.f * un - u[n];  u[n] = un;  pu0 = p[n];
                    ubE[r][cp] = ub[n];
                }
                {   // odd column: q_left is own register q[n-1]
                    const int n = 2 * k + 1;
                    const float div = (pu1 - p[n]) + (q[n - 1] - q[n]);
                    const float un  = (u[n] + TAUc * (fv[n] - div)) * INV;
                    ub[n] = 2.f * un - u[n];  u[n] = un;  pu1 = p[n];
                }
            }
            ubB[rg][c0] = ub[0];  ubB[rg][c0 + 1] = ub[1];
            __syncthreads();
        }
    }

    // ---- write interior result ----
#pragma unroll
    for (int k = 0; k < RPT; k++) {
#pragma unroll
        for (int e = 0; e < 2; e++) {
            const int r = rb + k, c = c0 + e;
            if (r >= TT && r < EXT_H - TT && c >= TT && c < EXT_W - TT)
                out[base + k * WW + e] = u[2 * k + e];
        }
    }
}

extern "C" void kernel_launch(void* const* d_in, const int* in_sizes, int n_in,
                              void* d_out, int out_size) {
    const float* f   = (const float*)d_in[0];
    const float* lam = (const float*)d_in[1];
    float* out = (float*)d_out;

    // Cooperative launch only for co-residency (the per-image barrier
    // requires all 32 CTAs of an image resident); no grid.sync used.
    void* args[] = { (void*)&f, (void*)&lam, (void*)&out };
    cudaLaunchCooperativeKernel((void*)tv_block,
                                dim3(NCTAS), dim3(NTHREADS),
                                args, 0, 0);
}